// round 14
// baseline (speedup 1.0000x reference)
#include <cuda_runtime.h>
#include <math.h>

#define N_ATOMS 21
#define DESC 210
#define D_PAD 256
#define M_ 64
#define T_ 8192
#define QCONST 0.22360679774997896f   /* sqrt(5)/10 */
#define INV_Q  4.47213595499957939f   /* 10/sqrt(5) */
#define COEF   (5.0f/300.0f)          /* 5/(3*sig^2), sig=10 */
#define STD_ 1.0f
#define C_   0.0f
#define N_TCHUNK 64                   /* pass B split-K chunks (t-chunks of 128) */
#define TCH 128                       /* t per pass-B chunk */

// ---------------- f32x2 packed helpers --------------------------------------
typedef unsigned long long u64t;
__device__ __forceinline__ u64t pack2(float v) {
    u64t r;
    asm("mov.b64 %0, {%1, %1};" : "=l"(r) : "f"(v));
    return r;
}
__device__ __forceinline__ u64t fma2(u64t a, u64t b, u64t c) {
    u64t d;
    asm("fma.rn.f32x2 %0, %1, %2, %3;" : "=l"(d) : "l"(a), "l"(b), "l"(c));
    return d;
}
__device__ __forceinline__ float2 unpack2(u64t v) {
    float2 f;
    asm("mov.b64 {%0, %1}, %2;" : "=f"(f.x), "=f"(f.y) : "l"(v));
    return f;
}

// ---------------- scratch (static device arrays; no allocation) -------------
__device__ float  g_qx[M_ * DESC];          // q / dist per (m, pair)
__device__ float  g_qnorm[M_];              // sum_d qx^2
__device__ float2 g_XJ[D_PAD * T_];         // {q*xs_train, Jx_alphas} transposed, d-padded
__device__ float2 g_C[M_ * T_];             // {c1, c2} per (m, t)
__device__ float  g_Gpart[N_TCHUNK * M_ * D_PAD];  // split-K partials of G
__device__ float  g_S1part[32 * M_];        // partial sums of c1 over t
__device__ float  g_E3part[32 * M_];        // partial sums of c2*dot over t

// pair index d -> (i, j), i > j, numpy tril_indices(k=-1) order
__device__ __forceinline__ void pair_ij(int d, int& i, int& j) {
    i = (int)((1.0f + sqrtf(8.0f * (float)d + 1.0f)) * 0.5f);
    while (i * (i - 1) / 2 > d) --i;
    while ((i + 1) * i / 2 <= d) ++i;
    j = d - i * (i - 1) / 2;
}

__global__ void k_dummy() {}

// ---------------- kernel 0: descriptors + qnorm + transpose (merged) ---------
__global__ void k_pre(const float* __restrict__ Rs,
                      const float* __restrict__ xs_train,
                      const float* __restrict__ J) {
    if (blockIdx.y == D_PAD / 32) {
        int m = blockIdx.x;
        if (m >= M_) return;
        int tid = threadIdx.y * 32 + threadIdx.x;
        __shared__ float sR[N_ATOMS * 3];
        __shared__ float red[256];
        if (tid < N_ATOMS * 3) sR[tid] = Rs[m * N_ATOMS * 3 + tid];
        __syncthreads();
        float v = 0.f;
        if (tid < DESC) {
            int i, j;
            pair_ij(tid, i, j);
            float dx = sR[i * 3 + 0] - sR[j * 3 + 0];
            float dy = sR[i * 3 + 1] - sR[j * 3 + 1];
            float dz = sR[i * 3 + 2] - sR[j * 3 + 2];
            float dist = sqrtf(dx * dx + dy * dy + dz * dz);
            float qx = QCONST / dist;
            g_qx[m * DESC + tid] = qx;
            v = qx * qx;
        }
        red[tid] = v;
        __syncthreads();
#pragma unroll
        for (int s = 128; s; s >>= 1) {
            if (tid < s) red[tid] += red[tid + s];
            __syncthreads();
        }
        if (tid == 0) g_qnorm[m] = red[0];
        return;
    }
    __shared__ float tA[32][33];
    __shared__ float tB[32][33];
    int t0 = blockIdx.x * 32;
    int d0 = blockIdx.y * 32;
    int tx = threadIdx.x;
#pragma unroll
    for (int k = 0; k < 4; k++) {
        int ty = threadIdx.y + k * 8;
        int t = t0 + ty;
        int d = d0 + tx;
        float a = 0.f, b = 0.f;
        if (d < DESC) {
            a = xs_train[t * DESC + d] * QCONST;
            b = J[t * DESC + d];
        }
        tA[ty][tx] = a;
        tB[ty][tx] = b;
    }
    __syncthreads();
#pragma unroll
    for (int k = 0; k < 4; k++) {
        int ty = threadIdx.y + k * 8;
        int d = d0 + ty;
        int t = t0 + tx;
        g_XJ[d * T_ + t] = make_float2(tA[tx][ty], tB[tx][ty]);
    }
}

// ---------------- kernel 1: pass A — GEMM-form coefficients (f32x2) ----------
#define ACH 10   /* d-chunk; 210 = 21 * 10 */
__global__ void __launch_bounds__(256) k_passA() {
    int t = blockIdx.x * 256 + threadIdx.x;
    int m0 = blockIdx.y * 16;
    __shared__ float qxs[DESC * 16];   // [d][mm]
    __shared__ float qn[16];
    if (threadIdx.x < 16) qn[threadIdx.x] = g_qnorm[m0 + threadIdx.x];
    for (int idx = threadIdx.x; idx < DESC * 16; idx += 256) {
        int d = idx >> 4, mm = idx & 15;
        qxs[idx] = g_qx[(m0 + mm) * DESC + d];
    }
    __syncthreads();

    u64t cross2[8], qxj2[8];
#pragma unroll
    for (int p = 0; p < 8; p++) { cross2[p] = 0ull; qxj2[p] = 0ull; }
    float nt = 0.f, dJ = 0.f;

    for (int dc = 0; dc < DESC; dc += ACH) {
        float2 xj[ACH];
#pragma unroll
        for (int k = 0; k < ACH; k++) xj[k] = g_XJ[(dc + k) * T_ + t];
#pragma unroll
        for (int k = 0; k < ACH; k++) {
            float xt = xj[k].x;
            float jv = xj[k].y;
            nt += xt * xt;
            dJ += xt * jv;
            u64t xt2 = pack2(xt);
            u64t jv2 = pack2(jv);
            const u64t* qp = (const u64t*)&qxs[(dc + k) * 16];
#pragma unroll
            for (int p = 0; p < 8; p++) {
                u64t qv = qp[p];
                cross2[p] = fma2(qv, xt2, cross2[p]);
                qxj2[p]   = fma2(qv, jv2, qxj2[p]);
            }
        }
    }

    float tc1[16], te3[16];
#pragma unroll
    for (int p = 0; p < 8; p++) {
        float2 cr = unpack2(cross2[p]);
        float2 qj = unpack2(qxj2[p]);
        float cra[2] = {cr.x, cr.y};
        float qja[2] = {qj.x, qj.y};
#pragma unroll
        for (int h = 0; h < 2; h++) {
            int mm = p * 2 + h;
            int m = m0 + mm;
            float xd2 = fmaxf(qn[mm] + nt - 2.f * cra[h], 0.f);
            float xdist = sqrtf(xd2);
            float ex = COEF * expf(-xdist);
            float dot = qja[h] - dJ;
            float c1 = ex * dot;
            float c2 = ex * (1.f + xdist);
            g_C[m * T_ + t] = make_float2(c1, c2);
            tc1[mm] = c1;
            te3[mm] = c2 * dot;
        }
    }

    // block-level partial sums of c1 and e3 for each of the 16 m's
    int lane = threadIdx.x & 31, wid = threadIdx.x >> 5;
    __shared__ float2 wred[8][16];
#pragma unroll
    for (int mm = 0; mm < 16; mm++) {
        float a = tc1[mm], b = te3[mm];
#pragma unroll
        for (int o = 16; o; o >>= 1) {
            a += __shfl_down_sync(0xffffffffu, a, o);
            b += __shfl_down_sync(0xffffffffu, b, o);
        }
        if (lane == 0) wred[wid][mm] = make_float2(a, b);
    }
    __syncthreads();
    if (threadIdx.x < 16) {
        float a = 0.f, b = 0.f;
#pragma unroll
        for (int w = 0; w < 8; w++) { a += wred[w][threadIdx.x].x; b += wred[w][threadIdx.x].y; }
        g_S1part[blockIdx.x * M_ + m0 + threadIdx.x] = a;
        g_E3part[blockIdx.x * M_ + m0 + threadIdx.x] = b;
    }
}

// ---------------- kernel 2: pass B — G = c1@qxt + c2@J (f32x2, split-K) ------
#define TSTEP 16
__global__ void __launch_bounds__(256) k_passB() {
    int d0 = blockIdx.x * 64;        // 4 d-tiles (padded region contributes 0)
    int tchunk = blockIdx.y;         // 64 t-chunks of 128
    int tbase = tchunk * TCH;
    __shared__ float c1s[TSTEP * 64];
    __shared__ float c2s[TSTEP * 64];
    __shared__ float xts[TSTEP * 64];
    __shared__ float jts[TSTEP * 64];
    int tid = threadIdx.x;
    int m0  = (tid & 15) * 4;
    int dl0 = (tid >> 4) * 4;
    int ttL = tid & 15;
    int rowL = tid >> 4;             // 0..15, +16 per i

    // acc2[di][p]: d-index di (dl0+di), m-pair p (m0+2p, m0+2p+1)
    u64t acc2[4][2];
#pragma unroll
    for (int di = 0; di < 4; di++) { acc2[di][0] = 0ull; acc2[di][1] = 0ull; }

    float2 pc[4], px[4];
#pragma unroll
    for (int i = 0; i < 4; i++) {
        int row = rowL + i * 16;
        int t = tbase + ttL;
        pc[i] = g_C[row * T_ + t];
        px[i] = g_XJ[(d0 + row) * T_ + t];
    }

    for (int ts = 0; ts < TCH; ts += TSTEP) {
        int sw = (ttL * 4) & 63;
#pragma unroll
        for (int i = 0; i < 4; i++) {
            int row = (rowL + i * 16) ^ sw;
            c1s[ttL * 64 + row] = pc[i].x;
            c2s[ttL * 64 + row] = pc[i].y;
            xts[ttL * 64 + row] = px[i].x;
            jts[ttL * 64 + row] = px[i].y;
        }
        __syncthreads();
        if (ts + TSTEP < TCH) {
#pragma unroll
            for (int i = 0; i < 4; i++) {
                int row = rowL + i * 16;
                int t = tbase + ts + TSTEP + ttL;
                pc[i] = g_C[row * T_ + t];
                px[i] = g_XJ[(d0 + row) * T_ + t];
            }
        }
#pragma unroll
        for (int tt = 0; tt < TSTEP; tt++) {
            int s = (tt * 4) & 63;
            // m-pairs of c1/c2 load directly as packed 64-bit lanes
            const u64t* c1p = (const u64t*)&c1s[tt * 64 + (m0 ^ s)];
            const u64t* c2p = (const u64t*)&c2s[tt * 64 + (m0 ^ s)];
            u64t c1q[2] = {c1p[0], c1p[1]};
            u64t c2q[2] = {c2p[0], c2p[1]};
            float4 xv = *(const float4*)&xts[tt * 64 + (dl0 ^ s)];
            float4 jv = *(const float4*)&jts[tt * 64 + (dl0 ^ s)];
            u64t xd2[4] = {pack2(xv.x), pack2(xv.y), pack2(xv.z), pack2(xv.w)};
            u64t jd2[4] = {pack2(jv.x), pack2(jv.y), pack2(jv.z), pack2(jv.w)};
#pragma unroll
            for (int di = 0; di < 4; di++) {
#pragma unroll
                for (int p = 0; p < 2; p++) {
                    acc2[di][p] = fma2(c1q[p], xd2[di], acc2[di][p]);
                    acc2[di][p] = fma2(c2q[p], jd2[di], acc2[di][p]);
                }
            }
        }
        __syncthreads();
    }
    float* dst = &g_Gpart[tchunk * (M_ * D_PAD)];
#pragma unroll
    for (int p = 0; p < 2; p++) {
        float2 a0 = unpack2(acc2[0][p]);
        float2 a1 = unpack2(acc2[1][p]);
        float2 a2 = unpack2(acc2[2][p]);
        float2 a3 = unpack2(acc2[3][p]);
        *(float4*)&dst[(m0 + 2*p)     * D_PAD + d0 + dl0] = make_float4(a0.x, a1.x, a2.x, a3.x);
        *(float4*)&dst[(m0 + 2*p + 1) * D_PAD + d0 + dl0] = make_float4(a0.y, a1.y, a2.y, a3.y);
    }
}

// ---------------- kernel 3: assemble forces + energies -----------------------
__global__ void k_final(const float* __restrict__ Rs, float* __restrict__ out) {
    int m = blockIdx.x;
    int tid = threadIdx.x;  // 256
    __shared__ float sR[N_ATOMS * 3];
    __shared__ float sF[N_ATOMS * 3];
    __shared__ float sS1, sEs;
    if (tid < N_ATOMS * 3) {
        sR[tid] = Rs[m * N_ATOMS * 3 + tid];
        sF[tid] = 0.f;
    }
    if (tid < 32) {
        float a = g_S1part[tid * M_ + m];
        float b = g_E3part[tid * M_ + m];
#pragma unroll
        for (int o = 16; o; o >>= 1) {
            a += __shfl_down_sync(0xffffffffu, a, o);
            b += __shfl_down_sync(0xffffffffu, b, o);
        }
        if (tid == 0) { sS1 = a; sEs = b; }
    }
    __syncthreads();
    if (tid < 64) {
        // each thread: 4 consecutive d's, float4 split-K reduce
        float4 G = make_float4(0.f, 0.f, 0.f, 0.f);
        const float* src = &g_Gpart[m * D_PAD + tid * 4];
#pragma unroll 8
        for (int ch = 0; ch < N_TCHUNK; ch++) {
            float4 v = *(const float4*)&src[ch * (M_ * D_PAD)];
            G.x += v.x; G.y += v.y; G.z += v.z; G.w += v.w;
        }
        float Ga[4] = {G.x, G.y, G.z, G.w};
#pragma unroll
        for (int k = 0; k < 4; k++) {
            int d = tid * 4 + k;
            if (d < DESC) {
                float qx = g_qx[m * DESC + d];
                float fsx = (qx * sS1 - Ga[k]) * STD_;
                float invd = qx * INV_Q;
                float w = fsx * invd * invd * invd;
                int i, j;
                pair_ij(d, i, j);
                float dx = sR[i * 3 + 0] - sR[j * 3 + 0];
                float dy = sR[i * 3 + 1] - sR[j * 3 + 1];
                float dz = sR[i * 3 + 2] - sR[j * 3 + 2];
                atomicAdd(&sF[i * 3 + 0],  w * dx);
                atomicAdd(&sF[i * 3 + 1],  w * dy);
                atomicAdd(&sF[i * 3 + 2],  w * dz);
                atomicAdd(&sF[j * 3 + 0], -w * dx);
                atomicAdd(&sF[j * 3 + 1], -w * dy);
                atomicAdd(&sF[j * 3 + 2], -w * dz);
            }
        }
    }
    __syncthreads();
    if (tid < N_ATOMS * 3)
        out[M_ + m * (N_ATOMS * 3) + tid] = sF[tid];
    if (tid == 0)
        out[m] = C_ + STD_ * sEs / QCONST;
}

// ---------------- launch -----------------------------------------------------
extern "C" void kernel_launch(void* const* d_in, const int* in_sizes, int n_in,
                              void* d_out, int out_size) {
    const float* Rs       = (const float*)d_in[0];
    const float* xs_train = (const float*)d_in[1];
    const float* J        = (const float*)d_in[2];
    float* out = (float*)d_out;

    // two no-op launches so ncu's fixed sample index lands on k_passA
    k_dummy<<<1, 32>>>();
    k_dummy<<<1, 32>>>();
    {
        dim3 tb(32, 8);
        dim3 tg(T_ / 32, D_PAD / 32 + 1);   // extra y-row runs descriptor blocks
        k_pre<<<tg, tb>>>(Rs, xs_train, J);
    }
    {
        dim3 ga(T_ / 256, M_ / 16);
        k_passA<<<ga, 256>>>();
    }
    {
        dim3 gb(D_PAD / 64, N_TCHUNK);
        k_passB<<<gb, 256>>>();
    }
    k_final<<<M_, 256>>>(Rs, out);
}

// round 15
// speedup vs baseline: 1.0078x; 1.0078x over previous
#include <cuda_runtime.h>
#include <math.h>

#define N_ATOMS 21
#define DESC 210
#define D_PAD 256
#define M_ 64
#define T_ 8192
#define QCONST 0.22360679774997896f   /* sqrt(5)/10 */
#define INV_Q  4.47213595499957939f   /* 10/sqrt(5) */
#define COEF   (5.0f/300.0f)          /* 5/(3*sig^2), sig=10 */
#define STD_ 1.0f
#define C_   0.0f
#define N_TCHUNK 64                   /* pass B split-K chunks (t-chunks of 128) */
#define TCH 128                       /* t per pass-B chunk */

// ---------------- f32x2 packed helpers --------------------------------------
typedef unsigned long long u64t;
__device__ __forceinline__ u64t pack2(float v) {
    u64t r;
    asm("mov.b64 %0, {%1, %1};" : "=l"(r) : "f"(v));
    return r;
}
__device__ __forceinline__ u64t fma2(u64t a, u64t b, u64t c) {
    u64t d;
    asm("fma.rn.f32x2 %0, %1, %2, %3;" : "=l"(d) : "l"(a), "l"(b), "l"(c));
    return d;
}
__device__ __forceinline__ float2 unpack2(u64t v) {
    float2 f;
    asm("mov.b64 {%0, %1}, %2;" : "=f"(f.x), "=f"(f.y) : "l"(v));
    return f;
}

// ---------------- scratch (static device arrays; no allocation) -------------
__device__ float  g_qx[M_ * DESC];          // q / dist per (m, pair)
__device__ float  g_qnorm[M_];              // sum_d qx^2
__device__ float2 g_XJ[D_PAD * T_];         // {q*xs_train, Jx_alphas} transposed, d-padded
__device__ float2 g_C[M_ * T_];             // {c1, c2} per (m, t)
__device__ float  g_Gpart[N_TCHUNK * M_ * D_PAD];  // split-K partials of G
__device__ float  g_S1part[32 * M_];        // partial sums of c1 over t
__device__ float  g_E3part[32 * M_];        // partial sums of c2*dot over t

// pair index d -> (i, j), i > j, numpy tril_indices(k=-1) order
__device__ __forceinline__ void pair_ij(int d, int& i, int& j) {
    i = (int)((1.0f + sqrtf(8.0f * (float)d + 1.0f)) * 0.5f);
    while (i * (i - 1) / 2 > d) --i;
    while ((i + 1) * i / 2 <= d) ++i;
    j = d - i * (i - 1) / 2;
}

__global__ void k_dummy() {}

// ---------------- kernel 0: descriptors + qnorm + transpose (merged) ---------
__global__ void k_pre(const float* __restrict__ Rs,
                      const float* __restrict__ xs_train,
                      const float* __restrict__ J) {
    if (blockIdx.y == D_PAD / 32) {
        int m = blockIdx.x;
        if (m >= M_) return;
        int tid = threadIdx.y * 32 + threadIdx.x;
        __shared__ float sR[N_ATOMS * 3];
        __shared__ float red[256];
        if (tid < N_ATOMS * 3) sR[tid] = Rs[m * N_ATOMS * 3 + tid];
        __syncthreads();
        float v = 0.f;
        if (tid < DESC) {
            int i, j;
            pair_ij(tid, i, j);
            float dx = sR[i * 3 + 0] - sR[j * 3 + 0];
            float dy = sR[i * 3 + 1] - sR[j * 3 + 1];
            float dz = sR[i * 3 + 2] - sR[j * 3 + 2];
            float dist = sqrtf(dx * dx + dy * dy + dz * dz);
            float qx = QCONST / dist;
            g_qx[m * DESC + tid] = qx;
            v = qx * qx;
        }
        red[tid] = v;
        __syncthreads();
#pragma unroll
        for (int s = 128; s; s >>= 1) {
            if (tid < s) red[tid] += red[tid + s];
            __syncthreads();
        }
        if (tid == 0) g_qnorm[m] = red[0];
        return;
    }
    __shared__ float tA[32][33];
    __shared__ float tB[32][33];
    int t0 = blockIdx.x * 32;
    int d0 = blockIdx.y * 32;
    int tx = threadIdx.x;
#pragma unroll
    for (int k = 0; k < 4; k++) {
        int ty = threadIdx.y + k * 8;
        int t = t0 + ty;
        int d = d0 + tx;
        float a = 0.f, b = 0.f;
        if (d < DESC) {
            a = xs_train[t * DESC + d] * QCONST;
            b = J[t * DESC + d];
        }
        tA[ty][tx] = a;
        tB[ty][tx] = b;
    }
    __syncthreads();
#pragma unroll
    for (int k = 0; k < 4; k++) {
        int ty = threadIdx.y + k * 8;
        int d = d0 + ty;
        int t = t0 + tx;
        g_XJ[d * T_ + t] = make_float2(tA[tx][ty], tB[tx][ty]);
    }
}

// ---------------- kernel 1: pass A — GEMM-form coefficients (f32x2) ----------
#define ACH 10   /* d-chunk; 210 = 21 * 10 */
__global__ void __launch_bounds__(256) k_passA() {
    int t = blockIdx.x * 256 + threadIdx.x;
    int m0 = blockIdx.y * 16;
    __shared__ float qxs[DESC * 16];   // [d][mm]
    __shared__ float qn[16];
    if (threadIdx.x < 16) qn[threadIdx.x] = g_qnorm[m0 + threadIdx.x];
    for (int idx = threadIdx.x; idx < DESC * 16; idx += 256) {
        int d = idx >> 4, mm = idx & 15;
        qxs[idx] = g_qx[(m0 + mm) * DESC + d];
    }
    __syncthreads();

    u64t cross2[8], qxj2[8];
#pragma unroll
    for (int p = 0; p < 8; p++) { cross2[p] = 0ull; qxj2[p] = 0ull; }
    float nt = 0.f, dJ = 0.f;

    for (int dc = 0; dc < DESC; dc += ACH) {
        float2 xj[ACH];
#pragma unroll
        for (int k = 0; k < ACH; k++) xj[k] = g_XJ[(dc + k) * T_ + t];
#pragma unroll
        for (int k = 0; k < ACH; k++) {
            float xt = xj[k].x;
            float jv = xj[k].y;
            nt += xt * xt;
            dJ += xt * jv;
            u64t xt2 = pack2(xt);
            u64t jv2 = pack2(jv);
            const u64t* qp = (const u64t*)&qxs[(dc + k) * 16];
#pragma unroll
            for (int p = 0; p < 8; p++) {
                u64t qv = qp[p];
                cross2[p] = fma2(qv, xt2, cross2[p]);
                qxj2[p]   = fma2(qv, jv2, qxj2[p]);
            }
        }
    }

    float tc1[16], te3[16];
#pragma unroll
    for (int p = 0; p < 8; p++) {
        float2 cr = unpack2(cross2[p]);
        float2 qj = unpack2(qxj2[p]);
        float cra[2] = {cr.x, cr.y};
        float qja[2] = {qj.x, qj.y};
#pragma unroll
        for (int h = 0; h < 2; h++) {
            int mm = p * 2 + h;
            int m = m0 + mm;
            float xd2 = fmaxf(qn[mm] + nt - 2.f * cra[h], 0.f);
            float xdist = sqrtf(xd2);
            float ex = COEF * expf(-xdist);
            float dot = qja[h] - dJ;
            float c1 = ex * dot;
            float c2 = ex * (1.f + xdist);
            g_C[m * T_ + t] = make_float2(c1, c2);
            tc1[mm] = c1;
            te3[mm] = c2 * dot;
        }
    }

    // block-level partial sums of c1 and e3 for each of the 16 m's
    int lane = threadIdx.x & 31, wid = threadIdx.x >> 5;
    __shared__ float2 wred[8][16];
#pragma unroll
    for (int mm = 0; mm < 16; mm++) {
        float a = tc1[mm], b = te3[mm];
#pragma unroll
        for (int o = 16; o; o >>= 1) {
            a += __shfl_down_sync(0xffffffffu, a, o);
            b += __shfl_down_sync(0xffffffffu, b, o);
        }
        if (lane == 0) wred[wid][mm] = make_float2(a, b);
    }
    __syncthreads();
    if (threadIdx.x < 16) {
        float a = 0.f, b = 0.f;
#pragma unroll
        for (int w = 0; w < 8; w++) { a += wred[w][threadIdx.x].x; b += wred[w][threadIdx.x].y; }
        g_S1part[blockIdx.x * M_ + m0 + threadIdx.x] = a;
        g_E3part[blockIdx.x * M_ + m0 + threadIdx.x] = b;
    }
}

// ---------------- kernel 2: pass B — G = c1@qxt + c2@J (f32x2, split-K) ------
#define TSTEP 16
__global__ void __launch_bounds__(256) k_passB() {
    int d0 = blockIdx.x * 64;        // 4 d-tiles (padded region contributes 0)
    int tchunk = blockIdx.y;         // 64 t-chunks of 128
    int tbase = tchunk * TCH;
    __shared__ float c1s[TSTEP * 64];
    __shared__ float c2s[TSTEP * 64];
    __shared__ float xts[TSTEP * 64];
    __shared__ float jts[TSTEP * 64];
    int tid = threadIdx.x;
    int m0  = (tid & 15) * 4;
    int dl0 = (tid >> 4) * 4;
    int ttL = tid & 15;
    int rowL = tid >> 4;             // 0..15, +16 per i

    // acc2[di][p]: d-index di (dl0+di), m-pair p (m0+2p, m0+2p+1)
    u64t acc2[4][2];
#pragma unroll
    for (int di = 0; di < 4; di++) { acc2[di][0] = 0ull; acc2[di][1] = 0ull; }

    float2 pc[4], px[4];
#pragma unroll
    for (int i = 0; i < 4; i++) {
        int row = rowL + i * 16;
        int t = tbase + ttL;
        pc[i] = g_C[row * T_ + t];
        px[i] = g_XJ[(d0 + row) * T_ + t];
    }

    for (int ts = 0; ts < TCH; ts += TSTEP) {
        int sw = (ttL * 4) & 63;
#pragma unroll
        for (int i = 0; i < 4; i++) {
            int row = (rowL + i * 16) ^ sw;
            c1s[ttL * 64 + row] = pc[i].x;
            c2s[ttL * 64 + row] = pc[i].y;
            xts[ttL * 64 + row] = px[i].x;
            jts[ttL * 64 + row] = px[i].y;
        }
        __syncthreads();
        if (ts + TSTEP < TCH) {
#pragma unroll
            for (int i = 0; i < 4; i++) {
                int row = rowL + i * 16;
                int t = tbase + ts + TSTEP + ttL;
                pc[i] = g_C[row * T_ + t];
                px[i] = g_XJ[(d0 + row) * T_ + t];
            }
        }
#pragma unroll
        for (int tt = 0; tt < TSTEP; tt++) {
            int s = (tt * 4) & 63;
            // m-pairs of c1/c2 load directly as packed 64-bit lanes
            const u64t* c1p = (const u64t*)&c1s[tt * 64 + (m0 ^ s)];
            const u64t* c2p = (const u64t*)&c2s[tt * 64 + (m0 ^ s)];
            u64t c1q[2] = {c1p[0], c1p[1]};
            u64t c2q[2] = {c2p[0], c2p[1]};
            float4 xv = *(const float4*)&xts[tt * 64 + (dl0 ^ s)];
            float4 jv = *(const float4*)&jts[tt * 64 + (dl0 ^ s)];
            u64t xd2[4] = {pack2(xv.x), pack2(xv.y), pack2(xv.z), pack2(xv.w)};
            u64t jd2[4] = {pack2(jv.x), pack2(jv.y), pack2(jv.z), pack2(jv.w)};
#pragma unroll
            for (int di = 0; di < 4; di++) {
#pragma unroll
                for (int p = 0; p < 2; p++) {
                    acc2[di][p] = fma2(c1q[p], xd2[di], acc2[di][p]);
                    acc2[di][p] = fma2(c2q[p], jd2[di], acc2[di][p]);
                }
            }
        }
        __syncthreads();
    }
    float* dst = &g_Gpart[tchunk * (M_ * D_PAD)];
#pragma unroll
    for (int p = 0; p < 2; p++) {
        float2 a0 = unpack2(acc2[0][p]);
        float2 a1 = unpack2(acc2[1][p]);
        float2 a2 = unpack2(acc2[2][p]);
        float2 a3 = unpack2(acc2[3][p]);
        *(float4*)&dst[(m0 + 2*p)     * D_PAD + d0 + dl0] = make_float4(a0.x, a1.x, a2.x, a3.x);
        *(float4*)&dst[(m0 + 2*p + 1) * D_PAD + d0 + dl0] = make_float4(a0.y, a1.y, a2.y, a3.y);
    }
}

// ---------------- kernel 3: assemble forces + energies -----------------------
__global__ void k_final(const float* __restrict__ Rs, float* __restrict__ out) {
    int m = blockIdx.x;
    int tid = threadIdx.x;  // 256
    __shared__ float sR[N_ATOMS * 3];
    __shared__ float sF[N_ATOMS * 3];
    __shared__ float sS1, sEs;
    if (tid < N_ATOMS * 3) {
        sR[tid] = Rs[m * N_ATOMS * 3 + tid];
        sF[tid] = 0.f;
    }
    if (tid < 32) {
        float a = g_S1part[tid * M_ + m];
        float b = g_E3part[tid * M_ + m];
#pragma unroll
        for (int o = 16; o; o >>= 1) {
            a += __shfl_down_sync(0xffffffffu, a, o);
            b += __shfl_down_sync(0xffffffffu, b, o);
        }
        if (tid == 0) { sS1 = a; sEs = b; }
    }
    __syncthreads();
    if (tid < 64) {
        // each thread: 4 consecutive d's, float4 split-K reduce
        float4 G = make_float4(0.f, 0.f, 0.f, 0.f);
        const float* src = &g_Gpart[m * D_PAD + tid * 4];
#pragma unroll 8
        for (int ch = 0; ch < N_TCHUNK; ch++) {
            float4 v = *(const float4*)&src[ch * (M_ * D_PAD)];
            G.x += v.x; G.y += v.y; G.z += v.z; G.w += v.w;
        }
        float Ga[4] = {G.x, G.y, G.z, G.w};
#pragma unroll
        for (int k = 0; k < 4; k++) {
            int d = tid * 4 + k;
            if (d < DESC) {
                float qx = g_qx[m * DESC + d];
                float fsx = (qx * sS1 - Ga[k]) * STD_;
                float invd = qx * INV_Q;
                float w = fsx * invd * invd * invd;
                int i, j;
                pair_ij(d, i, j);
                float dx = sR[i * 3 + 0] - sR[j * 3 + 0];
                float dy = sR[i * 3 + 1] - sR[j * 3 + 1];
                float dz = sR[i * 3 + 2] - sR[j * 3 + 2];
                atomicAdd(&sF[i * 3 + 0],  w * dx);
                atomicAdd(&sF[i * 3 + 1],  w * dy);
                atomicAdd(&sF[i * 3 + 2],  w * dz);
                atomicAdd(&sF[j * 3 + 0], -w * dx);
                atomicAdd(&sF[j * 3 + 1], -w * dy);
                atomicAdd(&sF[j * 3 + 2], -w * dz);
            }
        }
    }
    __syncthreads();
    if (tid < N_ATOMS * 3)
        out[M_ + m * (N_ATOMS * 3) + tid] = sF[tid];
    if (tid == 0)
        out[m] = C_ + STD_ * sEs / QCONST;
}

// ---------------- launch -----------------------------------------------------
extern "C" void kernel_launch(void* const* d_in, const int* in_sizes, int n_in,
                              void* d_out, int out_size) {
    const float* Rs       = (const float*)d_in[0];
    const float* xs_train = (const float*)d_in[1];
    const float* J        = (const float*)d_in[2];
    float* out = (float*)d_out;

    // two no-op launches so ncu's fixed sample index lands on k_passA
    k_dummy<<<1, 32>>>();
    k_dummy<<<1, 32>>>();
    {
        dim3 tb(32, 8);
        dim3 tg(T_ / 32, D_PAD / 32 + 1);   // extra y-row runs descriptor blocks
        k_pre<<<tg, tb>>>(Rs, xs_train, J);
    }
    {
        dim3 ga(T_ / 256, M_ / 16);
        k_passA<<<ga, 256>>>();
    }
    {
        dim3 gb(D_PAD / 64, N_TCHUNK);
        k_passB<<<gb, 256>>>();
    }
    k_final<<<M_, 256>>>(Rs, out);
}